// round 7
// baseline (speedup 1.0000x reference)
#include <cuda_runtime.h>
#include <cstdint>

#define BATCH 4
#define CIN   64
#define COUT  64
#define HW    224
#define NPIX  (HW * HW)          // 50176
#define KK    9
#define NBINS 10
#define KTOT  (CIN * KK)         // 576
#define NSTEP (KTOT / 8)         // 72 k-steps of 8
#define TILE_M 128
#define NTILE (NPIX / TILE_M)    // 392
#define NCONV (BATCH * NTILE)    // 1568
#define Y_ELEMS (BATCH * COUT * NPIX)
#define ESTRIDE 132              // epilogue smem stride (conflict-free)

// B fragments, tf32 bits, layout [chunk 18][nt 8][ks 4][lane 32][2]
__device__ uint32_t g_wfrag[18 * 2048];

__device__ __forceinline__ uint32_t f2tf32(float v) {
    uint32_t u;
    asm("cvt.rna.tf32.f32 %0, %1;" : "=r"(u) : "f"(v));
    return u;
}

#define MMA_TF32(d, a, b) \
    asm volatile("mma.sync.aligned.m16n8k8.row.col.f32.tf32.tf32.f32 " \
        "{%0,%1,%2,%3}, {%4,%5,%6,%7}, {%8,%9}, {%0,%1,%2,%3};" \
        : "+f"((d)[0]), "+f"((d)[1]), "+f"((d)[2]), "+f"((d)[3]) \
        : "r"((a).x), "r"((a).y), "r"((a).z), "r"((a).w), \
          "r"((b).x), "r"((b).y))

// ---------------------------------------------------------------------------
// Repack W -> fragment order (tf32-rounded); zero hist region of output.
// ---------------------------------------------------------------------------
__global__ void repack_w_kernel(const float* __restrict__ w,
                                float* __restrict__ out_hist) {
    int idx = blockIdx.x * blockDim.x + threadIdx.x;
    if (idx < 18 * 2048) {
        int pair = idx & 1;
        int lane = (idx >> 1) & 31;
        int ks   = (idx >> 6) & 3;
        int nt   = (idx >> 8) & 7;
        int c    = idx >> 11;
        int n = nt * 8 + (lane >> 2);
        int k = c * 32 + ks * 8 + (lane & 3) + pair * 4;
        g_wfrag[idx] = f2tf32(__ldg(&w[n * KTOT + k]));
    }
    if (idx < CIN * NBINS) out_hist[idx] = 0.0f;
}

// ---------------------------------------------------------------------------
// Implicit-GEMM conv, barrier-free mainloop: each lane gathers its own mma
// fragments from gmem (predicated LDG + cvt.rna), pipelined one k-step ahead.
// CTA: 128 pixels x 64 couts, 8 warps: (w&3)->M 32-block, (w>>2)->N 32-block.
// ---------------------------------------------------------------------------
__global__ __launch_bounds__(256, 2)
void conv_mma_kernel(const float* __restrict__ x,
                     const float* __restrict__ bias,
                     float* __restrict__ y) {
    __shared__ __align__(16) float E[63 * ESTRIDE + 128];   // epilogue stage
    __shared__ int   tab[KTOT];
    __shared__ float sbias[COUT];

    const int tid  = threadIdx.x;
    const int w    = tid >> 5;
    const int lane = tid & 31;

    for (int i = tid; i < KTOT; i += 256) {
        int ci = i / 9, tap = i - ci * 9;
        int dh = tap / 3, dw = tap - dh * 3;           // 0..2
        tab[i] = ci * NPIX + dh * HW + dw;             // offset from (hm-1, wm-1)
    }
    if (tid < COUT) sbias[tid] = __ldg(&bias[tid]);

    const int b    = blockIdx.x / NTILE;
    const int pix0 = (blockIdx.x % NTILE) * TILE_M;
    const float* xb = x + (size_t)b * CIN * NPIX;

    const int wm2 = (w & 3) * 2;
    const int wn4 = (w >> 2) * 4;
    const int g   = lane >> 2;       // fragment row group
    const int klo = lane & 3;        // fragment k low

    // 4 pixel slots: (tile wm2 rows g, g+8), (tile wm2+1 rows g, g+8)
    const float* ptr[4];
    unsigned tmask[4];               // 9-bit tap validity
    #pragma unroll
    for (int i = 0; i < 2; i++) {
        #pragma unroll
        for (int half = 0; half < 2; half++) {
            int s  = i * 2 + half;
            int m  = (wm2 + i) * 16 + g + half * 8;
            int pm = pix0 + m;
            int hm = pm / HW, wm = pm - hm * HW;
            ptr[s] = xb + hm * HW + wm - (HW + 1);
            int mk = 2 | 16;
            if (hm > 0)      mk |= 1;
            if (hm + 1 < HW) mk |= 4;
            if (wm > 0)      mk |= 8;
            if (wm + 1 < HW) mk |= 32;
            unsigned tm = 0;
            #pragma unroll
            for (int t = 0; t < 9; t++) {
                int dh = t / 3, dw = t - dh * 3;
                if (((mk >> dh) & 1) && ((mk >> (3 + dw)) & 1)) tm |= 1u << t;
            }
            tmask[s] = tm;
        }
    }

    __syncthreads();   // tab/sbias ready

    float d[2][4][4];
    #pragma unroll
    for (int mt = 0; mt < 2; mt++)
        #pragma unroll
        for (int nt = 0; nt < 4; nt++)
            #pragma unroll
            for (int k = 0; k < 4; k++) d[mt][nt][k] = 0.0f;

    // taps for current step: ta = (8*s + klo) % 9, tb = ta+4 pattern
    int ta = klo;            // step 0
    int tb = klo + 4;

    const uint2* bwp = (const uint2*)g_wfrag;

    // ---- fragment gather for step s given taps (ta,tb) ----
    auto loadA = [&](int s, int taa, int tbb, uint4& A0, uint4& A1) {
        const int offa = tab[s * 8 + klo];
        const int offb = tab[s * 8 + klo + 4];
        float va[4], vb[4];
        #pragma unroll
        for (int sl = 0; sl < 4; sl++) {
            va[sl] = 0.0f; vb[sl] = 0.0f;
            if ((tmask[sl] >> taa) & 1u) va[sl] = __ldg(ptr[sl] + offa);
            if ((tmask[sl] >> tbb) & 1u) vb[sl] = __ldg(ptr[sl] + offb);
        }
        A0 = make_uint4(f2tf32(va[0]), f2tf32(va[1]), f2tf32(vb[0]), f2tf32(vb[1]));
        A1 = make_uint4(f2tf32(va[2]), f2tf32(va[3]), f2tf32(vb[2]), f2tf32(vb[3]));
    };
    auto loadB = [&](int s, uint2* B) {
        const int c = s >> 2, ks = s & 3;
        #pragma unroll
        for (int nt = 0; nt < 4; nt++)
            B[nt] = __ldg(&bwp[(((c * 8 + wn4 + nt) * 4) + ks) * 32 + lane]);
    };

    uint4 cA0, cA1, nA0, nA1;
    uint2 cB[4], nB[4];
    loadA(0, ta, tb, cA0, cA1);
    loadB(0, cB);

    #pragma unroll 4
    for (int s = 0; s < NSTEP; s++) {
        // advance taps for step s+1: tap = (tap + 8) % 9 == tap - 1 mod 9
        int tan = (ta == 0) ? 8 : ta - 1;
        int tbn = (tb == 0) ? 8 : tb - 1;
        if (s + 1 < NSTEP) {
            loadA(s + 1, tan, tbn, nA0, nA1);
            loadB(s + 1, nB);
        }
        #pragma unroll
        for (int nt = 0; nt < 4; nt++) {
            MMA_TF32(d[0][nt], cA0, cB[nt]);
            MMA_TF32(d[1][nt], cA1, cB[nt]);
        }
        cA0 = nA0; cA1 = nA1;
        #pragma unroll
        for (int nt = 0; nt < 4; nt++) cB[nt] = nB[nt];
        ta = tan; tb = tbn;
    }

    // ---- epilogue: stage via smem for coalesced 128B stores ----
    const int rbase = (w & 3) * 32 + g;
    const int cbase = wn4 * 8 + klo * 2;
    #pragma unroll
    for (int mt = 0; mt < 2; mt++) {
        #pragma unroll
        for (int nt = 0; nt < 4; nt++) {
            int r0 = rbase + mt * 16;
            int c0 = cbase + nt * 8;
            E[c0 * ESTRIDE + r0]           = d[mt][nt][0];
            E[(c0 + 1) * ESTRIDE + r0]     = d[mt][nt][1];
            E[c0 * ESTRIDE + r0 + 8]       = d[mt][nt][2];
            E[(c0 + 1) * ESTRIDE + r0 + 8] = d[mt][nt][3];
        }
    }
    __syncthreads();

    float* yb = y + (size_t)b * COUT * NPIX + pix0;
    const int p4 = lane * 4;
    #pragma unroll
    for (int i = 0; i < 8; i++) {
        int co = w * 8 + i;
        float4 v = *(const float4*)&E[co * ESTRIDE + p4];
        float bv = sbias[co];
        v.x += bv; v.y += bv; v.z += bv; v.w += bv;
        *(float4*)&yb[(size_t)co * NPIX + p4] = v;
    }
}

// ---------------------------------------------------------------------------
// Histogram: warp-ballot byte-SIMD separable window-sum, direct float output.
// product(b,c,ho,wo,k)==0 iff pad || x==0 || w[0,c,k]==0.
// ---------------------------------------------------------------------------
__device__ __forceinline__ unsigned zprow_calc(unsigned nib, int l) {
    unsigned nl = __shfl_sync(0xFFFFFFFFu, nib, (l == 0) ? 29 : (l - 1));
    unsigned nr = __shfl_sync(0xFFFFFFFFu, nib, (l == 27) ? 28 : ((l + 1) & 31));
    unsigned ext = ((nl >> 3) & 1u) | (nib << 1) | ((nr & 1u) << 5);
    unsigned z0 = __popc(ext & 7u);
    unsigned z1 = __popc((ext >> 1) & 7u);
    unsigned z2 = __popc((ext >> 2) & 7u);
    unsigned z3 = __popc((ext >> 3) & 7u);
    return z0 | (z1 << 8) | (z2 << 16) | (z3 << 24);
}

__global__ __launch_bounds__(256)
void hist_count_kernel(const float* __restrict__ x, const float* __restrict__ w,
                       float* __restrict__ out_hist) {
    const int bid = blockIdx.x;
    const int rc = bid & 3;
    const int c  = (bid >> 2) & 63;
    const int b  = bid >> 8;

    __shared__ int sbin[NBINS];
    const int tid = threadIdx.x;
    if (tid < NBINS) sbin[tid] = 0;

    bool anywz = false;
    #pragma unroll
    for (int k = 0; k < KK; k++) anywz |= (__ldg(&w[c * KK + k]) == 0.0f);
    __syncthreads();

    const float* xp = x + (size_t)(b * CIN + c) * NPIX;

    if (!anywz) {
        const int wd = tid >> 5, l = tid & 31;
        const int half = wd & 1, sub = wd >> 1;
        const int r0 = rc * 56 + sub * 14;
        int colb; bool ldok;
        if (l < 28)      { colb = 112 * half + 4 * l;  ldok = true; }
        else if (l == 28){ colb = 112 * half + 112;    ldok = (half == 0); }
        else if (l == 29){ colb = 112 * half - 4;      ldok = (half == 1); }
        else             { colb = 0;                   ldok = false; }

        auto vget = [&](int row) -> float4 {
            if (ldok && row >= 0 && row < HW)
                return __ldg((const float4*)(xp + row * HW + colb));
            return make_float4(1.f, 1.f, 1.f, 1.f);
        };
        auto nibof = [&](int row, float4 v) -> unsigned {
            if (!ldok || row < 0 || row >= HW) return 0xFu;
            return (v.x == 0.f ? 1u : 0u) | (v.y == 0.f ? 2u : 0u) |
                   (v.z == 0.f ? 4u : 0u) | (v.w == 0.f ? 8u : 0u);
        };

        int cnt0 = 0;
        float4 va = vget(r0 - 1);
        float4 vb = vget(r0);
        float4 vnext = vget(r0 + 1);
        unsigned zpm = zprow_calc(nibof(r0 - 1, va), l);
        unsigned zpc = zprow_calc(nibof(r0, vb), l);

        for (int r = r0; r < r0 + 14; r++) {
            float4 vd = vget(r + 2);
            unsigned zpn = zprow_calc(nibof(r + 1, vnext), l);
            unsigned z4 = zpm + zpc + zpn;   // byte-SIMD (max 9/byte)
            if (l < 28) {
                if (z4 == 0) cnt0 += 4;
                else {
                    #pragma unroll
                    for (int j = 0; j < 4; j++) {
                        unsigned bz = (z4 >> (8 * j)) & 0xFFu;
                        if (bz == 0) cnt0++;
                        else atomicAdd(&sbin[bz], 1);
                    }
                }
            }
            zpm = zpc; zpc = zpn; vnext = vd;
        }
        if (l < 28 && cnt0) atomicAdd(&sbin[0], cnt0);
    } else {
        bool wz[KK];
        #pragma unroll
        for (int k = 0; k < KK; k++) wz[k] = (__ldg(&w[c * KK + k]) == 0.0f);
        const int col = tid;
        const int r0q = rc * 56;
        if (col < HW) {
            for (int row = r0q; row < r0q + 56; row++) {
                int z = 0;
                #pragma unroll
                for (int kh = 0; kh < 3; kh++)
                    #pragma unroll
                    for (int kw = 0; kw < 3; kw++) {
                        int gy = row + kh - 1, gx = col + kw - 1;
                        bool zero = (gy < 0 || gy >= HW || gx < 0 || gx >= HW)
                            ? true
                            : (wz[kh * 3 + kw] || __ldg(&xp[gy * HW + gx]) == 0.0f);
                        z += zero ? 1 : 0;
                    }
                atomicAdd(&sbin[z], 1);
            }
        }
    }

    __syncthreads();
    if (tid < NBINS && sbin[tid])
        atomicAdd(&out_hist[c * NBINS + tid], (float)sbin[tid]);
}

// ---------------------------------------------------------------------------
extern "C" void kernel_launch(void* const* d_in, const int* in_sizes, int n_in,
                              void* d_out, int out_size) {
    const float* x    = (const float*)d_in[0];   // (4,64,224,224)
    const float* wgt  = (const float*)d_in[1];   // (64,64,3,3)
    const float* bias = (const float*)d_in[2];   // (64,)
    float* y    = (float*)d_out;
    float* hist = (float*)d_out + (size_t)Y_ELEMS;

    repack_w_kernel<<<(18 * 2048 + 255) / 256, 256>>>(wgt, hist);
    conv_mma_kernel<<<NCONV, 256>>>(x, bias, y);
    hist_count_kernel<<<BATCH * CIN * 4, 256>>>(x, wgt, hist);
}

// round 8
// speedup vs baseline: 1.2129x; 1.2129x over previous
#include <cuda_runtime.h>
#include <cstdint>

#define BATCH 4
#define CIN   64
#define COUT  64
#define HW    224
#define NPIX  (HW * HW)          // 50176
#define KK    9
#define NBINS 10
#define KTOT  (CIN * KK)         // 576
#define KC    32
#define NCHUNK (KTOT / KC)       // 18
#define TILE_M 128
#define NTILE (NPIX / TILE_M)    // 392
#define NCONV (BATCH * NTILE)    // 1568
#define Y_ELEMS (BATCH * COUT * NPIX)
#define ESTRIDE 132              // epilogue smem stride (conflict-free)

// B fragments, f16x2 pairs: [k16-step 36][nt 8][lane 32][reg 2]
__device__ uint32_t g_wfrag[36 * 512];

// pack two f32 -> f16x2 (lo = first k, hi = second k)
__device__ __forceinline__ uint32_t pack_f16x2(float lo, float hi) {
    uint32_t d;
    asm("cvt.rn.f16x2.f32 %0, %1, %2;" : "=r"(d) : "f"(hi), "f"(lo));
    return d;
}

#define MMA_F16(d, a, b) \
    asm volatile("mma.sync.aligned.m16n8k16.row.col.f32.f16.f16.f32 " \
        "{%0,%1,%2,%3}, {%4,%5,%6,%7}, {%8,%9}, {%0,%1,%2,%3};" \
        : "+f"((d)[0]), "+f"((d)[1]), "+f"((d)[2]), "+f"((d)[3]) \
        : "r"((a).x), "r"((a).y), "r"((a).z), "r"((a).w), \
          "r"((b).x), "r"((b).y))

// ---------------------------------------------------------------------------
// Repack W (64,576) -> m16n8k16 B-fragment order fp16; zero hist output.
// idx = ((s*8 + nt)*32 + lane)*2 + reg
//   n = nt*8 + (lane>>2);  k = s*16 + (lane&3)*2 + reg*8
// ---------------------------------------------------------------------------
__global__ void repack_w_kernel(const float* __restrict__ w,
                                float* __restrict__ out_hist) {
    int idx = blockIdx.x * blockDim.x + threadIdx.x;
    if (idx < 36 * 512) {
        int reg  = idx & 1;
        int lane = (idx >> 1) & 31;
        int nt   = (idx >> 6) & 7;
        int s    = idx >> 9;
        int n = nt * 8 + (lane >> 2);
        int k = s * 16 + (lane & 3) * 2 + reg * 8;
        float w0 = __ldg(&w[n * KTOT + k]);
        float w1 = __ldg(&w[n * KTOT + k + 1]);
        g_wfrag[idx] = pack_f16x2(w0, w1);
    }
    if (idx < CIN * NBINS) out_hist[idx] = 0.0f;
}

// ---------------------------------------------------------------------------
// Implicit-GEMM conv via mma.sync fp16 (m16n8k16), f32 accumulate.
// CTA: 128 pixels x 64 couts. 8 warps: (w&3)->M 32-block, (w>>2)->N 32-block.
// Producer: thread q=tid>>5 stages m-tile q's A fragments for both k16 steps.
// ---------------------------------------------------------------------------
struct ConvSh {
    uint4 sA[2][512];    // 16 KB: [buf][(mt*2+ks)*32+lane]
    int   tab[KTOT];
    float sbias[COUT];
};

__global__ __launch_bounds__(256, 2)
void conv_mma_kernel(const float* __restrict__ x,
                     const float* __restrict__ bias,
                     float* __restrict__ y) {
    __shared__ __align__(16) union { ConvSh c; float E[8448]; } sm;

    uint4 (*sA)[512] = sm.c.sA;
    int*   tab   = sm.c.tab;
    float* sbias = sm.c.sbias;

    const int tid  = threadIdx.x;
    const int w    = tid >> 5;      // warp / producer slot q
    const int lane = tid & 31;
    const int g    = lane >> 2;
    const int klo  = lane & 3;

    for (int i = tid; i < KTOT; i += 256) {
        int ci = i / 9, tap = i - ci * 9;
        int dh = tap / 3, dw = tap - dh * 3;
        tab[i] = (ci * NPIX + dh * HW + dw) | (tap << 24);
    }
    if (tid < COUT) sbias[tid] = __ldg(&bias[tid]);

    const int b    = blockIdx.x / NTILE;
    const int pix0 = (blockIdx.x % NTILE) * TILE_M;
    const float* xb = x + (size_t)b * CIN * NPIX;

    // ---- producer pixel slots: rows g and g+8 of m-tile q=w ----
    const float* ptrP[2];
    unsigned tmaskP[2];
    #pragma unroll
    for (int half = 0; half < 2; half++) {
        int m  = w * 16 + g + half * 8;
        int pm = pix0 + m;
        int hm = pm / HW, wm = pm - hm * HW;
        ptrP[half] = xb + hm * HW + wm - (HW + 1);
        int mk = 2 | 16;
        if (hm > 0)      mk |= 1;
        if (hm + 1 < HW) mk |= 4;
        if (wm > 0)      mk |= 8;
        if (wm + 1 < HW) mk |= 32;
        unsigned tm = 0;
        #pragma unroll
        for (int t = 0; t < 9; t++) {
            int dh = t / 3, dw = t - dh * 3;
            if (((mk >> dh) & 1) && ((mk >> (3 + dw)) & 1)) tm |= 1u << t;
        }
        tmaskP[half] = tm;
    }

    __syncthreads();   // tab/sbias ready

    const int kb = 2 * klo;

    // stage fragments for chunk c into registers (S0 = ks0, S1 = ks1)
    auto loadA = [&](int c, uint4& S0, uint4& S1) {
        float v[2][8];
        #pragma unroll
        for (int j = 0; j < 8; j++) {
            const int koff = kb + (j & 1) + (j >> 1) * 8;   // kb,kb+1,kb+8,kb+9,kb+16,...
            const int e    = tab[c * KC + koff];
            const int off  = e & 0xFFFFFF;
            const int tap  = e >> 24;
            #pragma unroll
            for (int h = 0; h < 2; h++)
                v[h][j] = ((tmaskP[h] >> tap) & 1u) ? __ldg(ptrP[h] + off) : 0.0f;
        }
        S0 = make_uint4(pack_f16x2(v[0][0], v[0][1]), pack_f16x2(v[1][0], v[1][1]),
                        pack_f16x2(v[0][2], v[0][3]), pack_f16x2(v[1][2], v[1][3]));
        S1 = make_uint4(pack_f16x2(v[0][4], v[0][5]), pack_f16x2(v[1][4], v[1][5]),
                        pack_f16x2(v[0][6], v[0][7]), pack_f16x2(v[1][6], v[1][7]));
    };

    const int wm2 = (w & 3) * 2;
    const int wn4 = (w >> 2) * 4;
    const uint2* bwp = (const uint2*)g_wfrag;

    float d[2][4][4];
    #pragma unroll
    for (int mt = 0; mt < 2; mt++)
        #pragma unroll
        for (int nt = 0; nt < 4; nt++)
            #pragma unroll
            for (int k = 0; k < 4; k++) d[mt][nt][k] = 0.0f;

    uint4 S0, S1;
    loadA(0, S0, S1);

    for (int c = 0; c < NCHUNK; c++) {
        const int p = c & 1;
        sA[p][(w * 2 + 0) * 32 + lane] = S0;
        sA[p][(w * 2 + 1) * 32 + lane] = S1;
        __syncthreads();
        if (c + 1 < NCHUNK) loadA(c + 1, S0, S1);

        #pragma unroll
        for (int ks = 0; ks < 2; ks++) {
            uint4 A0 = sA[p][(wm2 * 2 + ks) * 32 + lane];
            uint4 A1 = sA[p][((wm2 + 1) * 2 + ks) * 32 + lane];
            const int s36 = c * 2 + ks;
            #pragma unroll
            for (int nt = 0; nt < 4; nt++) {
                uint2 bv = __ldg(&bwp[((s36 * 8 + wn4 + nt) * 32) + lane]);
                MMA_F16(d[0][nt], A0, bv);
                MMA_F16(d[1][nt], A1, bv);
            }
        }
    }

    // ---- epilogue: read bias to regs, stage D via smem, coalesced stores ----
    float breg[8];
    #pragma unroll
    for (int i = 0; i < 8; i++) breg[i] = sbias[w * 8 + i];
    __syncthreads();                         // all smem reads done; reuse as E

    float* E = sm.E;
    const int rbase = (w & 3) * 32 + g;
    const int cbase = wn4 * 8 + klo * 2;
    #pragma unroll
    for (int mt = 0; mt < 2; mt++) {
        #pragma unroll
        for (int nt = 0; nt < 4; nt++) {
            int r0 = rbase + mt * 16;
            int c0 = cbase + nt * 8;
            E[c0 * ESTRIDE + r0]           = d[mt][nt][0];
            E[(c0 + 1) * ESTRIDE + r0]     = d[mt][nt][1];
            E[c0 * ESTRIDE + r0 + 8]       = d[mt][nt][2];
            E[(c0 + 1) * ESTRIDE + r0 + 8] = d[mt][nt][3];
        }
    }
    __syncthreads();

    float* yb = y + (size_t)b * COUT * NPIX + pix0;
    const int p4 = lane * 4;
    #pragma unroll
    for (int i = 0; i < 8; i++) {
        int co = w * 8 + i;
        float4 v = *(const float4*)&E[co * ESTRIDE + p4];
        float bv = breg[i];
        v.x += bv; v.y += bv; v.z += bv; v.w += bv;
        *(float4*)&yb[(size_t)co * NPIX + p4] = v;
    }
}

// ---------------------------------------------------------------------------
// Histogram: warp-ballot byte-SIMD separable window-sum, direct float output.
// product(b,c,ho,wo,k)==0 iff pad || x==0 || w[0,c,k]==0.
// ---------------------------------------------------------------------------
__device__ __forceinline__ unsigned zprow_calc(unsigned nib, int l) {
    unsigned nl = __shfl_sync(0xFFFFFFFFu, nib, (l == 0) ? 29 : (l - 1));
    unsigned nr = __shfl_sync(0xFFFFFFFFu, nib, (l == 27) ? 28 : ((l + 1) & 31));
    unsigned ext = ((nl >> 3) & 1u) | (nib << 1) | ((nr & 1u) << 5);
    unsigned z0 = __popc(ext & 7u);
    unsigned z1 = __popc((ext >> 1) & 7u);
    unsigned z2 = __popc((ext >> 2) & 7u);
    unsigned z3 = __popc((ext >> 3) & 7u);
    return z0 | (z1 << 8) | (z2 << 16) | (z3 << 24);
}

__global__ __launch_bounds__(256)
void hist_count_kernel(const float* __restrict__ x, const float* __restrict__ w,
                       float* __restrict__ out_hist) {
    const int bid = blockIdx.x;
    const int rc = bid & 3;
    const int c  = (bid >> 2) & 63;
    const int b  = bid >> 8;

    __shared__ int sbin[NBINS];
    const int tid = threadIdx.x;
    if (tid < NBINS) sbin[tid] = 0;

    bool anywz = false;
    #pragma unroll
    for (int k = 0; k < KK; k++) anywz |= (__ldg(&w[c * KK + k]) == 0.0f);
    __syncthreads();

    const float* xp = x + (size_t)(b * CIN + c) * NPIX;

    if (!anywz) {
        const int wd = tid >> 5, l = tid & 31;
        const int half = wd & 1, sub = wd >> 1;
        const int r0 = rc * 56 + sub * 14;
        int colb; bool ldok;
        if (l < 28)      { colb = 112 * half + 4 * l;  ldok = true; }
        else if (l == 28){ colb = 112 * half + 112;    ldok = (half == 0); }
        else if (l == 29){ colb = 112 * half - 4;      ldok = (half == 1); }
        else             { colb = 0;                   ldok = false; }

        auto vget = [&](int row) -> float4 {
            if (ldok && row >= 0 && row < HW)
                return __ldg((const float4*)(xp + row * HW + colb));
            return make_float4(1.f, 1.f, 1.f, 1.f);
        };
        auto nibof = [&](int row, float4 v) -> unsigned {
            if (!ldok || row < 0 || row >= HW) return 0xFu;
            return (v.x == 0.f ? 1u : 0u) | (v.y == 0.f ? 2u : 0u) |
                   (v.z == 0.f ? 4u : 0u) | (v.w == 0.f ? 8u : 0u);
        };

        int cnt0 = 0;
        float4 va = vget(r0 - 1);
        float4 vb = vget(r0);
        float4 vnext = vget(r0 + 1);
        unsigned zpm = zprow_calc(nibof(r0 - 1, va), l);
        unsigned zpc = zprow_calc(nibof(r0, vb), l);

        for (int r = r0; r < r0 + 14; r++) {
            float4 vd = vget(r + 2);
            unsigned zpn = zprow_calc(nibof(r + 1, vnext), l);
            unsigned z4 = zpm + zpc + zpn;   // byte-SIMD (max 9/byte)
            if (l < 28) {
                if (z4 == 0) cnt0 += 4;
                else {
                    #pragma unroll
                    for (int j = 0; j < 4; j++) {
                        unsigned bz = (z4 >> (8 * j)) & 0xFFu;
                        if (bz == 0) cnt0++;
                        else atomicAdd(&sbin[bz], 1);
                    }
                }
            }
            zpm = zpc; zpc = zpn; vnext = vd;
        }
        if (l < 28 && cnt0) atomicAdd(&sbin[0], cnt0);
    } else {
        bool wz[KK];
        #pragma unroll
        for (int k = 0; k < KK; k++) wz[k] = (__ldg(&w[c * KK + k]) == 0.0f);
        const int col = tid;
        const int r0q = rc * 56;
        if (col < HW) {
            for (int row = r0q; row < r0q + 56; row++) {
                int z = 0;
                #pragma unroll
                for (int kh = 0; kh < 3; kh++)
                    #pragma unroll
                    for (int kw = 0; kw < 3; kw++) {
                        int gy = row + kh - 1, gx = col + kw - 1;
                        bool zero = (gy < 0 || gy >= HW || gx < 0 || gx >= HW)
                            ? true
                            : (wz[kh * 3 + kw] || __ldg(&xp[gy * HW + gx]) == 0.0f);
                        z += zero ? 1 : 0;
                    }
                atomicAdd(&sbin[z], 1);
            }
        }
    }

    __syncthreads();
    if (tid < NBINS && sbin[tid])
        atomicAdd(&out_hist[c * NBINS + tid], (float)sbin[tid]);
}

// ---------------------------------------------------------------------------
extern "C" void kernel_launch(void* const* d_in, const int* in_sizes, int n_in,
                              void* d_out, int out_size) {
    const float* x    = (const float*)d_in[0];   // (4,64,224,224)
    const float* wgt  = (const float*)d_in[1];   // (64,64,3,3)
    const float* bias = (const float*)d_in[2];   // (64,)
    float* y    = (float*)d_out;
    float* hist = (float*)d_out + (size_t)Y_ELEMS;

    repack_w_kernel<<<(36 * 512 + 255) / 256, 256>>>(wgt, hist);
    conv_mma_kernel<<<NCONV, 256>>>(x, bias, y);
    hist_count_kernel<<<BATCH * CIN * 4, 256>>>(x, wgt, hist);
}